// round 12
// baseline (speedup 1.0000x reference)
#include <cuda_runtime.h>
#include <cuda_bf16.h>
#include <cstdint>
#include <cstring>

// Problem shapes (fixed by reference)
#define BSZ   16
#define SEQL  1024
#define HIN   1024
#define HOUT  1024
#define PDIM  512
#define MROWS (BSZ * SEQL)   // 16384

// ---------------------------------------------------------------------------
// Device scratch (static allocation — no cudaMalloc allowed)
// ---------------------------------------------------------------------------
__device__ float         g_Bu [(size_t)MROWS * PDIM];   // GEMM1 out / scan in (fp32)
__device__ float         g_T  [(size_t)BSZ * SEQL];     // per-batch cumsum of t
__device__ __nv_bfloat16 g_xhi[(size_t)MROWS * PDIM];   // scan out hi
__device__ __nv_bfloat16 g_xlo[(size_t)MROWS * PDIM];   // scan out lo
__device__ __nv_bfloat16 g_Bhi[(size_t)PDIM * HIN];
__device__ __nv_bfloat16 g_Blo[(size_t)PDIM * HIN];
__device__ __nv_bfloat16 g_Chi[(size_t)HOUT * PDIM];
__device__ __nv_bfloat16 g_Clo[(size_t)HOUT * PDIM];

// ---------------------------------------------------------------------------
// PTX helpers (base ISA only)
// ---------------------------------------------------------------------------
__device__ __forceinline__ uint32_t smem_u32(const void* p) {
    uint32_t a;
    asm("{ .reg .u64 t; cvta.to.shared.u64 t, %1; cvt.u32.u64 %0, t; }"
        : "=r"(a) : "l"(p));
    return a;
}

__device__ __forceinline__ void cp16(uint32_t dst, const void* src) {
    asm volatile("cp.async.cg.shared.global [%0], [%1], 16;"
                 :: "r"(dst), "l"(src) : "memory");
}
#define CP_COMMIT() asm volatile("cp.async.commit_group;" ::: "memory")
#define CP_WAIT1()  asm volatile("cp.async.wait_group 1;" ::: "memory")

__device__ __forceinline__ void ldsm4(uint32_t& r0, uint32_t& r1,
                                      uint32_t& r2, uint32_t& r3,
                                      uint32_t addr) {
    asm volatile("ldmatrix.sync.aligned.m8n8.x4.shared.b16 {%0,%1,%2,%3}, [%4];"
                 : "=r"(r0), "=r"(r1), "=r"(r2), "=r"(r3) : "r"(addr));
}

__device__ __forceinline__ void mma16816(float* c, const uint32_t* a,
                                         uint32_t b0, uint32_t b1) {
    asm volatile(
        "mma.sync.aligned.m16n8k16.row.col.f32.bf16.bf16.f32 "
        "{%0,%1,%2,%3}, {%4,%5,%6,%7}, {%8,%9}, {%0,%1,%2,%3};"
        : "+f"(c[0]), "+f"(c[1]), "+f"(c[2]), "+f"(c[3])
        : "r"(a[0]), "r"(a[1]), "r"(a[2]), "r"(a[3]), "r"(b0), "r"(b1));
}

__device__ __forceinline__ void sts64(uint32_t addr, uint32_t v0, uint32_t v1) {
    asm volatile("st.shared.v2.b32 [%0], {%1, %2};"
                 :: "r"(addr), "r"(v0), "r"(v1) : "memory");
}

// ---------------------------------------------------------------------------
// fp32 -> (hi, lo) bf16 split, vectorized prepass (weights only)
// ---------------------------------------------------------------------------
__global__ void split_kernel(const float4* __restrict__ src,
                             uint2* __restrict__ dhi,
                             uint2* __restrict__ dlo, int n4) {
    int i      = blockIdx.x * blockDim.x + threadIdx.x;
    int stride = gridDim.x * blockDim.x;
    for (; i < n4; i += stride) {
        float4 v = src[i];
        __nv_bfloat162 h01 = __floats2bfloat162_rn(v.x, v.y);
        __nv_bfloat162 h23 = __floats2bfloat162_rn(v.z, v.w);
        float r0 = v.x - __bfloat162float(h01.x);
        float r1 = v.y - __bfloat162float(h01.y);
        float r2 = v.z - __bfloat162float(h23.x);
        float r3 = v.w - __bfloat162float(h23.y);
        __nv_bfloat162 l01 = __floats2bfloat162_rn(r0, r1);
        __nv_bfloat162 l23 = __floats2bfloat162_rn(r2, r3);
        uint2 ho, lo;
        memcpy(&ho.x, &h01, 4); memcpy(&ho.y, &h23, 4);
        memcpy(&lo.x, &l01, 4); memcpy(&lo.y, &l23, 4);
        dhi[i] = ho;
        dlo[i] = lo;
    }
}

// ---------------------------------------------------------------------------
// Tensor-core NT GEMM (HMMA, bf16-split emulation of fp32):
//   C[M,N] = (Ahi+Alo)[M,K] * (Bhi+Blo)[N,K]^T   (dropping lo*lo)
//   optional epilogue: += dvec[n] * U2[m,n]
// CTA tile 64x128, k-chunk 64, 128 threads (4 warps: 2 in M x 2 in N),
// warp tile 32x64. 2-stage pipeline; 2 CTAs/SM cover chunk-boundary drains.
// AFP32=true: A given as fp32; each chunk is cp.async-staged (16KB) and
// split to bf16 hi/lo in-kernel (fuses the split_u prepass into GEMM1).
// ---------------------------------------------------------------------------
#define KCH    64
#define APART  8192                  // 64 rows x 128 bytes
#define BPART  16384                 // 128 rows x 128 bytes
#define BUFB   (2 * APART + 2 * BPART)   // 48 KB per stage
#define STAGEF 16384                 // fp32 A staging (AFP32 path)
#define SMEM_G1 (STAGEF + 2 * BUFB)  // 112 KB
#define SMEM_G2 (2 * BUFB)           // 96 KB

#define OFF_AHI 0
#define OFF_ALO (APART)
#define OFF_BHI (2 * APART)
#define OFF_BLO (2 * APART + BPART)

template <int ROWS>
__device__ __forceinline__ void issue_part(const __nv_bfloat16* g, int K,
                                           uint32_t pbase, int tid) {
#pragma unroll
    for (int q = 0; q < ROWS / 16; ++q) {
        int seg = tid + q * 128;
        int row = seg >> 3;
        int sc  = seg & 7;
        uint32_t boff = (uint32_t)(row * 128 + sc * 16);
        uint32_t sw   = boff ^ ((boff >> 3) & 0x70);
        cp16(pbase + sw, (const char*)g + (size_t)row * (K * 2) + sc * 16);
    }
}

// Stage one 64x64 fp32 A-chunk (linear layout, 1024 16B segs)
__device__ __forceinline__ void issue_a32(const float* g, int K,
                                          uint32_t stage, int tid) {
#pragma unroll
    for (int q = 0; q < 8; ++q) {
        int seg = tid + q * 128;
        int row = seg >> 4;
        int sc  = seg & 15;
        cp16(stage + (uint32_t)seg * 16,
             (const char*)g + (size_t)row * (K * 4) + sc * 16);
    }
}

// Convert staged fp32 A-chunk -> swizzled bf16 hi/lo tiles
__device__ __forceinline__ void convert_a32(const char* dsm, uint32_t aHi,
                                            uint32_t aLo, int tid) {
#pragma unroll
    for (int q = 0; q < 8; ++q) {
        int seg = tid + q * 128;
        int row = seg >> 4;
        int sc  = seg & 15;
        float4 v = *reinterpret_cast<const float4*>(dsm + seg * 16);
        __nv_bfloat162 h01 = __floats2bfloat162_rn(v.x, v.y);
        __nv_bfloat162 h23 = __floats2bfloat162_rn(v.z, v.w);
        float r0 = v.x - __bfloat162float(h01.x);
        float r1 = v.y - __bfloat162float(h01.y);
        float r2 = v.z - __bfloat162float(h23.x);
        float r3 = v.w - __bfloat162float(h23.y);
        __nv_bfloat162 l01 = __floats2bfloat162_rn(r0, r1);
        __nv_bfloat162 l23 = __floats2bfloat162_rn(r2, r3);
        uint32_t h0, h1, l0, l1;
        memcpy(&h0, &h01, 4); memcpy(&h1, &h23, 4);
        memcpy(&l0, &l01, 4); memcpy(&l1, &l23, 4);
        uint32_t boff = (uint32_t)(row * 128 + sc * 8);
        uint32_t sw   = boff ^ ((boff >> 3) & 0x70);
        sts64(aHi + sw, h0, h1);
        sts64(aLo + sw, l0, l1);
    }
}

template <bool AFP32>
__global__ __launch_bounds__(128, 2)
void gemm_mma_kernel(const float* __restrict__ A32,
                     const __nv_bfloat16* __restrict__ Ahi,
                     const __nv_bfloat16* __restrict__ Alo,
                     const __nv_bfloat16* __restrict__ Bhi,
                     const __nv_bfloat16* __restrict__ Blo,
                     float* __restrict__ C,
                     int M, int N, int K,
                     const float* __restrict__ dvec,
                     const float* __restrict__ U2)
{
    extern __shared__ __align__(1024) char dsm[];
    const uint32_t sb    = smem_u32(dsm);
    const uint32_t stage = sb;                              // fp32 staging (AFP32)
    const uint32_t bufs  = AFP32 ? (sb + STAGEF) : sb;
    const char*    dstag = dsm;

    const int tid  = threadIdx.x;
    const int lane = tid & 31;
    const int warp = tid >> 5;      // 0..3
    const int wm   = warp & 1;      // 2 warps along M (32 rows each)
    const int wn   = warp >> 1;     // 2 warps along N (64 cols each)
    const int m0   = blockIdx.y * 64;
    const int n0   = blockIdx.x * 128;

    const float*         gA32 = AFP32 ? (A32 + (size_t)m0 * K) : nullptr;
    const __nv_bfloat16* gAh  = AFP32 ? nullptr : (Ahi + (size_t)m0 * K);
    const __nv_bfloat16* gAl  = AFP32 ? nullptr : (Alo + (size_t)m0 * K);
    const __nv_bfloat16* gBh  = Bhi + (size_t)n0 * K;
    const __nv_bfloat16* gBl  = Blo + (size_t)n0 * K;

    float acc[2][8][4];
#pragma unroll
    for (int a = 0; a < 2; a++)
#pragma unroll
        for (int b = 0; b < 8; b++)
#pragma unroll
            for (int c = 0; c < 4; c++) acc[a][b][c] = 0.0f;

    const int nch = K / KCH;   // 16 (GEMM1) or 8 (GEMM2)

    // Prologue
    if (AFP32) {
        // G0 = {B0, A32(0)}, G1 = {B1}
        issue_part<128>(gBh, K, bufs + OFF_BHI, tid);
        issue_part<128>(gBl, K, bufs + OFF_BLO, tid);
        issue_a32(gA32, K, stage, tid);
        CP_COMMIT();
        issue_part<128>(gBh + KCH, K, bufs + BUFB + OFF_BHI, tid);
        issue_part<128>(gBl + KCH, K, bufs + BUFB + OFF_BLO, tid);
        CP_COMMIT();
    } else {
        issue_part<64> (gAh, K, bufs + OFF_AHI, tid);
        issue_part<64> (gAl, K, bufs + OFF_ALO, tid);
        issue_part<128>(gBh, K, bufs + OFF_BHI, tid);
        issue_part<128>(gBl, K, bufs + OFF_BLO, tid);
        CP_COMMIT();
        issue_part<64> (gAh + KCH, K, bufs + BUFB + OFF_AHI, tid);
        issue_part<64> (gAl + KCH, K, bufs + BUFB + OFF_ALO, tid);
        issue_part<128>(gBh + KCH, K, bufs + BUFB + OFF_BHI, tid);
        issue_part<128>(gBl + KCH, K, bufs + BUFB + OFF_BLO, tid);
        CP_COMMIT();
    }

    const int lrow   = lane & 15;
    const int lkhalf = (lane & 16) ? 16 : 0;   // byte offset selecting k+8 blocks

    for (int s = 0; s < nch; ++s) {
        CP_WAIT1();            // B(s) (and A(s) / A32(s)) resident
        __syncthreads();

        const uint32_t buf = bufs + (uint32_t)(s & 1) * BUFB;
        const uint32_t aHi = buf + OFF_AHI;
        const uint32_t aLo = buf + OFF_ALO;
        const uint32_t bHi = buf + OFF_BHI;
        const uint32_t bLo = buf + OFF_BLO;

        if (AFP32) {
            // Split staged fp32 chunk s into this stage's bf16 A tiles.
            convert_a32(dstag, aHi, aLo, tid);
            __syncthreads();   // conversion visible; staging buffer free
            // Refill staging with A32(s+1); lone group so wait-counts stay aligned.
            if (s + 1 < nch) issue_a32(gA32 + (s + 1) * KCH, K, stage, tid);
            CP_COMMIT();       // group {A32(s+1)}
        }

#pragma unroll
        for (int ks = 0; ks < 4; ++ks) {
            uint32_t ah[2][4], al[2][4], bh[4][4], bl[4][4];
#pragma unroll
            for (int mt = 0; mt < 2; ++mt) {
                int row = wm * 32 + mt * 16 + lrow;
                uint32_t boff = (uint32_t)(row * 128 + ks * 32 + lkhalf);
                uint32_t sw   = boff ^ ((boff >> 3) & 0x70);
                ldsm4(ah[mt][0], ah[mt][1], ah[mt][2], ah[mt][3], aHi + sw);
                ldsm4(al[mt][0], al[mt][1], al[mt][2], al[mt][3], aLo + sw);
            }
#pragma unroll
            for (int g = 0; g < 4; ++g) {
                int row = wn * 64 + g * 16 + lrow;
                uint32_t boff = (uint32_t)(row * 128 + ks * 32 + lkhalf);
                uint32_t sw   = boff ^ ((boff >> 3) & 0x70);
                ldsm4(bh[g][0], bh[g][1], bh[g][2], bh[g][3], bHi + sw);
                ldsm4(bl[g][0], bl[g][1], bl[g][2], bl[g][3], bLo + sw);
            }
#pragma unroll
            for (int mt = 0; mt < 2; ++mt)
#pragma unroll
                for (int nt = 0; nt < 8; ++nt) {
                    const int g = nt >> 1, e = nt & 1;
                    mma16816(acc[mt][nt], ah[mt], bh[g][e], bh[g][e + 2]);
                    mma16816(acc[mt][nt], ah[mt], bl[g][e], bl[g][e + 2]);
                    mma16816(acc[mt][nt], al[mt], bh[g][e], bh[g][e + 2]);
                }
        }

        __syncthreads();       // all warps done reading buf before refill

        if (s + 2 < nch) {
            if (AFP32) {
                issue_part<128>(gBh + (s + 2) * KCH, K, buf + OFF_BHI, tid);
                issue_part<128>(gBl + (s + 2) * KCH, K, buf + OFF_BLO, tid);
            } else {
                issue_part<64> (gAh + (s + 2) * KCH, K, buf + OFF_AHI, tid);
                issue_part<64> (gAl + (s + 2) * KCH, K, buf + OFF_ALO, tid);
                issue_part<128>(gBh + (s + 2) * KCH, K, buf + OFF_BHI, tid);
                issue_part<128>(gBl + (s + 2) * KCH, K, buf + OFF_BLO, tid);
            }
        }
        CP_COMMIT();           // group {B(s+2)} (possibly empty)
    }

    // Epilogue: fragment (m16n8) c0,c1 -> row gID, cols 2*tIG,+1 ; c2,c3 -> row gID+8
    const int gID = lane >> 2;
    const int tIG = lane & 3;
#pragma unroll
    for (int mt = 0; mt < 2; ++mt)
#pragma unroll
        for (int half = 0; half < 2; ++half) {
            const int m = m0 + wm * 32 + mt * 16 + gID + half * 8;
#pragma unroll
            for (int nt = 0; nt < 8; ++nt) {
                const int n = n0 + wn * 64 + nt * 8 + tIG * 2;
                float v0 = acc[mt][nt][half * 2 + 0];
                float v1 = acc[mt][nt][half * 2 + 1];
                if (dvec != nullptr) {
                    const float* up = U2 + (size_t)m * N + n;
                    v0 = fmaf(dvec[n],     up[0], v0);
                    v1 = fmaf(dvec[n + 1], up[1], v1);
                }
                float2 o = make_float2(v0, v1);
                *reinterpret_cast<float2*>(C + (size_t)m * N + n) = o;
            }
        }
}

// ---------------------------------------------------------------------------
// Per-batch inclusive cumsum of timesteps (16 blocks x 1024 threads).
// ---------------------------------------------------------------------------
__global__ __launch_bounds__(1024)
void tsum_kernel(const float* __restrict__ t, float* __restrict__ T)
{
    __shared__ float sh[SEQL];
    const int b = blockIdx.x, i = threadIdx.x;
    sh[i] = t[b * SEQL + i];
    __syncthreads();
#pragma unroll
    for (int off = 1; off < SEQL; off <<= 1) {
        float add = (i >= off) ? sh[i - off] : 0.0f;
        __syncthreads();
        sh[i] += add;
        __syncthreads();
    }
    T[b * SEQL + i] = sh[i];
}

// ---------------------------------------------------------------------------
// Parallel scan over L.
// Uses A_cum(l) = exp(Lam*step * T(l)) (CLIP_MAX never binds since Lam<0,
// Delta>=0), so z = gamma*Bu/(A_cum+1e-9) is element-wise and s = cumsum(z).
// Block (32 p-lanes, 8 l-threads); 16 chunks of 64 l; smem carry chain.
// grid (BSZ, PDIM/32). Writes x pre-split as bf16 hi/lo for GEMM2.
// ---------------------------------------------------------------------------
__global__ __launch_bounds__(256)
void s5_scan_par(const float* __restrict__ timesteps,
                 const float* __restrict__ Tg,
                 const float* __restrict__ Lambda_raw,
                 const float* __restrict__ log_step,
                 const float* __restrict__ Bu,
                 __nv_bfloat16* __restrict__ xhi,
                 __nv_bfloat16* __restrict__ xlo)
{
    const int b  = blockIdx.x;
    const int tx = threadIdx.x;                 // 0..31 (p lane)
    const int ty = threadIdx.y;                 // 0..7  (l group)
    const int p  = blockIdx.y * 32 + tx;

    __shared__ float t_sh[SEQL];
    __shared__ float T_sh[SEQL];
    __shared__ float part[2][8][33];
    __shared__ float carry[2][32];

    const int tid = ty * 32 + tx;
    for (int i = tid; i < SEQL; i += 256) {
        t_sh[i] = timesteps[b * SEQL + i];
        T_sh[i] = Tg[b * SEQL + i];
    }
    if (ty == 0) carry[0][tx] = 0.0f;

    float raw  = Lambda_raw[p];
    float sp   = fmaxf(raw, 0.0f) + log1pf(expf(-fabsf(raw)));
    float Lam  = -(sp + 1e-3f);
    float step = expf(log_step[p]);             // STEP_RESCALE == 1
    float K1   = Lam * step;
    float invLam = 1.0f / Lam;

    const size_t base = ((size_t)b * SEQL) * PDIM + p;

    float zt[8], ac[8];
    for (int c = 0; c < 16; ++c) {
        const int l0 = c * 64 + ty * 8;
        float lsum = 0.0f;
#pragma unroll
        for (int k = 0; k < 8; ++k) {
            const int l = l0 + k;
            float A_cum = __expf(K1 * T_sh[l]);
            float A_bar = __expf(K1 * t_sh[l]);
            float gamma = (A_bar - 1.0f) * invLam;   // |Lam| >= 1e-3 always
            float bu    = Bu[base + (size_t)l * PDIM];
            float z     = __fdividef(gamma * bu, A_cum + 1e-9f);
            lsum += z;
            zt[k] = lsum;        // inclusive local prefix
            ac[k] = A_cum;
        }
        part[c & 1][ty][tx] = lsum;
        __syncthreads();
        float cr = carry[c & 1][tx];
#pragma unroll
        for (int y = 0; y < 7; ++y)
            if (y < ty) cr += part[c & 1][y][tx];
        if (ty == 7) carry[(c + 1) & 1][tx] = cr + part[c & 1][7][tx];
#pragma unroll
        for (int k = 0; k < 8; ++k) {
            const int l = l0 + k;
            float x = ac[k] * (cr + zt[k]);
            __nv_bfloat16 h = __float2bfloat16(x);
            xhi[base + (size_t)l * PDIM] = h;
            xlo[base + (size_t)l * PDIM] =
                __float2bfloat16(x - __bfloat162float(h));
        }
    }
}

// ---------------------------------------------------------------------------
// Launch: split(B,C) + tsum -> GEMM1 (fused u-split) -> scan -> GEMM2
// Input order (metadata): u, timesteps, Lambda_raw, log_step, B, C, D
// ---------------------------------------------------------------------------
extern "C" void kernel_launch(void* const* d_in, const int* in_sizes, int n_in,
                              void* d_out, int out_size)
{
    const float* u          = (const float*)d_in[0];
    const float* timesteps  = (const float*)d_in[1];
    const float* Lambda_raw = (const float*)d_in[2];
    const float* log_step   = (const float*)d_in[3];
    const float* Bmat       = (const float*)d_in[4];
    const float* Cmat       = (const float*)d_in[5];
    const float* Dvec       = (const float*)d_in[6];
    float* out = (float*)d_out;

    float *Bu, *Tg;
    __nv_bfloat16 *xhi, *xlo, *Bhi, *Blo, *Chi, *Clo;
    cudaGetSymbolAddress((void**)&Bu,  g_Bu);
    cudaGetSymbolAddress((void**)&Tg,  g_T);
    cudaGetSymbolAddress((void**)&xhi, g_xhi);
    cudaGetSymbolAddress((void**)&xlo, g_xlo);
    cudaGetSymbolAddress((void**)&Bhi, g_Bhi);
    cudaGetSymbolAddress((void**)&Blo, g_Blo);
    cudaGetSymbolAddress((void**)&Chi, g_Chi);
    cudaGetSymbolAddress((void**)&Clo, g_Clo);

    cudaFuncSetAttribute(gemm_mma_kernel<true>,
                         cudaFuncAttributeMaxDynamicSharedMemorySize, SMEM_G1);
    cudaFuncSetAttribute(gemm_mma_kernel<false>,
                         cudaFuncAttributeMaxDynamicSharedMemorySize, SMEM_G2);

    // Prepass: split weight matrices, cumsum of t (all tiny)
    {
        int n4b = PDIM * HIN / 4;
        split_kernel<<<512, 256>>>((const float4*)Bmat, (uint2*)Bhi, (uint2*)Blo, n4b);
        int n4c = HOUT * PDIM / 4;
        split_kernel<<<512, 256>>>((const float4*)Cmat, (uint2*)Chi, (uint2*)Clo, n4c);
        tsum_kernel<<<BSZ, SEQL>>>(timesteps, Tg);
    }

    // GEMM1: Bu[M, P] = u[M, HIN] @ B[P, HIN]^T  (u split fused in-kernel)
    {
        dim3 grid(PDIM / 128, MROWS / 64);
        gemm_mma_kernel<true><<<grid, 128, SMEM_G1>>>(
            u, nullptr, nullptr, Bhi, Blo, Bu,
            MROWS, PDIM, HIN, nullptr, nullptr);
    }

    // Parallel scan: Bu -> x_seq (emitted pre-split as bf16 hi/lo)
    {
        dim3 grid(BSZ, PDIM / 32);
        dim3 blk(32, 8);
        s5_scan_par<<<grid, blk>>>(timesteps, Tg, Lambda_raw, log_step,
                                   Bu, xhi, xlo);
    }

    // GEMM2: ys[M, HOUT] = x[M, P] @ C[HOUT, P]^T + D * u
    {
        dim3 grid(HOUT / 128, MROWS / 64);
        gemm_mma_kernel<false><<<grid, 128, SMEM_G2>>>(
            nullptr, xhi, xlo, Chi, Clo, out,
            MROWS, HOUT, PDIM, Dvec, u);
    }
}

// round 13
// speedup vs baseline: 1.0282x; 1.0282x over previous
#include <cuda_runtime.h>
#include <cuda_bf16.h>
#include <cstdint>
#include <cstring>

// Problem shapes (fixed by reference)
#define BSZ   16
#define SEQL  1024
#define HIN   1024
#define HOUT  1024
#define PDIM  512
#define MROWS (BSZ * SEQL)   // 16384

// ---------------------------------------------------------------------------
// Device scratch (static allocation — no cudaMalloc allowed)
// ---------------------------------------------------------------------------
__device__ float         g_Bu [(size_t)MROWS * PDIM];   // GEMM1 out / scan in (fp32)
__device__ float         g_T  [(size_t)BSZ * SEQL];     // per-batch cumsum of t
__device__ __nv_bfloat16 g_xhi[(size_t)MROWS * PDIM];   // scan out hi
__device__ __nv_bfloat16 g_xlo[(size_t)MROWS * PDIM];   // scan out lo
__device__ __nv_bfloat16 g_Bhi[(size_t)PDIM * HIN];
__device__ __nv_bfloat16 g_Blo[(size_t)PDIM * HIN];
__device__ __nv_bfloat16 g_Chi[(size_t)HOUT * PDIM];
__device__ __nv_bfloat16 g_Clo[(size_t)HOUT * PDIM];

// ---------------------------------------------------------------------------
// PTX helpers (base ISA only)
// ---------------------------------------------------------------------------
__device__ __forceinline__ uint32_t smem_u32(const void* p) {
    uint32_t a;
    asm("{ .reg .u64 t; cvta.to.shared.u64 t, %1; cvt.u32.u64 %0, t; }"
        : "=r"(a) : "l"(p));
    return a;
}

__device__ __forceinline__ void cp16(uint32_t dst, const void* src) {
    asm volatile("cp.async.cg.shared.global [%0], [%1], 16;"
                 :: "r"(dst), "l"(src) : "memory");
}
#define CP_COMMIT() asm volatile("cp.async.commit_group;" ::: "memory")
#define CP_WAIT1()  asm volatile("cp.async.wait_group 1;" ::: "memory")

__device__ __forceinline__ void ldsm4(uint32_t& r0, uint32_t& r1,
                                      uint32_t& r2, uint32_t& r3,
                                      uint32_t addr) {
    asm volatile("ldmatrix.sync.aligned.m8n8.x4.shared.b16 {%0,%1,%2,%3}, [%4];"
                 : "=r"(r0), "=r"(r1), "=r"(r2), "=r"(r3) : "r"(addr));
}

__device__ __forceinline__ void mma16816(float* c, const uint32_t* a,
                                         uint32_t b0, uint32_t b1) {
    asm volatile(
        "mma.sync.aligned.m16n8k16.row.col.f32.bf16.bf16.f32 "
        "{%0,%1,%2,%3}, {%4,%5,%6,%7}, {%8,%9}, {%0,%1,%2,%3};"
        : "+f"(c[0]), "+f"(c[1]), "+f"(c[2]), "+f"(c[3])
        : "r"(a[0]), "r"(a[1]), "r"(a[2]), "r"(a[3]), "r"(b0), "r"(b1));
}

__device__ __forceinline__ void sts64(uint32_t addr, uint32_t v0, uint32_t v1) {
    asm volatile("st.shared.v2.b32 [%0], {%1, %2};"
                 :: "r"(addr), "r"(v0), "r"(v1) : "memory");
}

// ---------------------------------------------------------------------------
// fp32 -> (hi, lo) bf16 split, vectorized prepass (weights only)
// ---------------------------------------------------------------------------
__global__ void split_kernel(const float4* __restrict__ src,
                             uint2* __restrict__ dhi,
                             uint2* __restrict__ dlo, int n4) {
    int i      = blockIdx.x * blockDim.x + threadIdx.x;
    int stride = gridDim.x * blockDim.x;
    for (; i < n4; i += stride) {
        float4 v = src[i];
        __nv_bfloat162 h01 = __floats2bfloat162_rn(v.x, v.y);
        __nv_bfloat162 h23 = __floats2bfloat162_rn(v.z, v.w);
        float r0 = v.x - __bfloat162float(h01.x);
        float r1 = v.y - __bfloat162float(h01.y);
        float r2 = v.z - __bfloat162float(h23.x);
        float r3 = v.w - __bfloat162float(h23.y);
        __nv_bfloat162 l01 = __floats2bfloat162_rn(r0, r1);
        __nv_bfloat162 l23 = __floats2bfloat162_rn(r2, r3);
        uint2 ho, lo;
        memcpy(&ho.x, &h01, 4); memcpy(&ho.y, &h23, 4);
        memcpy(&lo.x, &l01, 4); memcpy(&lo.y, &l23, 4);
        dhi[i] = ho;
        dlo[i] = lo;
    }
}

// ---------------------------------------------------------------------------
// Tensor-core NT GEMM (HMMA, bf16-split emulation of fp32):
//   C[M,N] = (Ahi+Alo)[M,K] * (Bhi+Blo)[N,K]^T   (dropping lo*lo)
//   optional epilogue: += dvec[n] * U2[m,n]
// CTA tile 64x128, k-chunk 64, 256 threads (8 warps: 2 in M x 4 in N),
// warp tile 32x32. 2-stage pipeline, 2 CTAs/SM -> 4 warps/SMSP from two
// independent CTAs to hide LDSM latency and chunk-boundary drains.
// AFP32=true: A arrives fp32, staged via cp.async and split in-kernel.
// ---------------------------------------------------------------------------
#define KCH    64
#define APART  8192                  // 64 rows x 128 bytes
#define BPART  16384                 // 128 rows x 128 bytes
#define BUFB   (2 * APART + 2 * BPART)   // 48 KB per stage
#define STAGEF 16384                 // fp32 A staging (AFP32 path)
#define SMEM_G1 (STAGEF + 2 * BUFB)  // 112 KB
#define SMEM_G2 (2 * BUFB)           // 96 KB
#define NTHR   256

#define OFF_AHI 0
#define OFF_ALO (APART)
#define OFF_BHI (2 * APART)
#define OFF_BLO (2 * APART + BPART)

template <int ROWS>
__device__ __forceinline__ void issue_part(const __nv_bfloat16* g, int K,
                                           uint32_t pbase, int tid) {
#pragma unroll
    for (int q = 0; q < ROWS * 8 / NTHR; ++q) {
        int seg = tid + q * NTHR;
        int row = seg >> 3;
        int sc  = seg & 7;
        uint32_t boff = (uint32_t)(row * 128 + sc * 16);
        uint32_t sw   = boff ^ ((boff >> 3) & 0x70);
        cp16(pbase + sw, (const char*)g + (size_t)row * (K * 2) + sc * 16);
    }
}

// Stage one 64x64 fp32 A-chunk (linear layout, 1024 16B segs)
__device__ __forceinline__ void issue_a32(const float* g, int K,
                                          uint32_t stage, int tid) {
#pragma unroll
    for (int q = 0; q < 1024 / NTHR; ++q) {
        int seg = tid + q * NTHR;
        int row = seg >> 4;
        int sc  = seg & 15;
        cp16(stage + (uint32_t)seg * 16,
             (const char*)g + (size_t)row * (K * 4) + sc * 16);
    }
}

// Convert staged fp32 A-chunk -> swizzled bf16 hi/lo tiles
__device__ __forceinline__ void convert_a32(const char* dsm, uint32_t aHi,
                                            uint32_t aLo, int tid) {
#pragma unroll
    for (int q = 0; q < 1024 / NTHR; ++q) {
        int seg = tid + q * NTHR;
        int row = seg >> 4;
        int sc  = seg & 15;
        float4 v = *reinterpret_cast<const float4*>(dsm + seg * 16);
        __nv_bfloat162 h01 = __floats2bfloat162_rn(v.x, v.y);
        __nv_bfloat162 h23 = __floats2bfloat162_rn(v.z, v.w);
        float r0 = v.x - __bfloat162float(h01.x);
        float r1 = v.y - __bfloat162float(h01.y);
        float r2 = v.z - __bfloat162float(h23.x);
        float r3 = v.w - __bfloat162float(h23.y);
        __nv_bfloat162 l01 = __floats2bfloat162_rn(r0, r1);
        __nv_bfloat162 l23 = __floats2bfloat162_rn(r2, r3);
        uint32_t h0, h1, l0, l1;
        memcpy(&h0, &h01, 4); memcpy(&h1, &h23, 4);
        memcpy(&l0, &l01, 4); memcpy(&l1, &l23, 4);
        uint32_t boff = (uint32_t)(row * 128 + sc * 8);
        uint32_t sw   = boff ^ ((boff >> 3) & 0x70);
        sts64(aHi + sw, h0, h1);
        sts64(aLo + sw, l0, l1);
    }
}

template <bool AFP32>
__global__ __launch_bounds__(NTHR, 2)
void gemm_mma_kernel(const float* __restrict__ A32,
                     const __nv_bfloat16* __restrict__ Ahi,
                     const __nv_bfloat16* __restrict__ Alo,
                     const __nv_bfloat16* __restrict__ Bhi,
                     const __nv_bfloat16* __restrict__ Blo,
                     float* __restrict__ C,
                     int M, int N, int K,
                     const float* __restrict__ dvec,
                     const float* __restrict__ U2)
{
    extern __shared__ __align__(1024) char dsm[];
    const uint32_t sb    = smem_u32(dsm);
    const uint32_t stage = sb;                              // fp32 staging (AFP32)
    const uint32_t bufs  = AFP32 ? (sb + STAGEF) : sb;
    const char*    dstag = dsm;

    const int tid  = threadIdx.x;
    const int lane = tid & 31;
    const int warp = tid >> 5;      // 0..7
    const int wm   = warp & 1;      // 2 warps along M (32 rows each)
    const int wn   = warp >> 1;     // 4 warps along N (32 cols each)
    const int m0   = blockIdx.y * 64;
    const int n0   = blockIdx.x * 128;

    const float*         gA32 = AFP32 ? (A32 + (size_t)m0 * K) : nullptr;
    const __nv_bfloat16* gAh  = AFP32 ? nullptr : (Ahi + (size_t)m0 * K);
    const __nv_bfloat16* gAl  = AFP32 ? nullptr : (Alo + (size_t)m0 * K);
    const __nv_bfloat16* gBh  = Bhi + (size_t)n0 * K;
    const __nv_bfloat16* gBl  = Blo + (size_t)n0 * K;

    float acc[2][4][4];
#pragma unroll
    for (int a = 0; a < 2; a++)
#pragma unroll
        for (int b = 0; b < 4; b++)
#pragma unroll
            for (int c = 0; c < 4; c++) acc[a][b][c] = 0.0f;

    const int nch = K / KCH;   // 16 (GEMM1) or 8 (GEMM2)

    // Prologue
    if (AFP32) {
        // G0 = {B0, A32(0)}, G1 = {B1}
        issue_part<128>(gBh, K, bufs + OFF_BHI, tid);
        issue_part<128>(gBl, K, bufs + OFF_BLO, tid);
        issue_a32(gA32, K, stage, tid);
        CP_COMMIT();
        issue_part<128>(gBh + KCH, K, bufs + BUFB + OFF_BHI, tid);
        issue_part<128>(gBl + KCH, K, bufs + BUFB + OFF_BLO, tid);
        CP_COMMIT();
    } else {
        issue_part<64> (gAh, K, bufs + OFF_AHI, tid);
        issue_part<64> (gAl, K, bufs + OFF_ALO, tid);
        issue_part<128>(gBh, K, bufs + OFF_BHI, tid);
        issue_part<128>(gBl, K, bufs + OFF_BLO, tid);
        CP_COMMIT();
        issue_part<64> (gAh + KCH, K, bufs + BUFB + OFF_AHI, tid);
        issue_part<64> (gAl + KCH, K, bufs + BUFB + OFF_ALO, tid);
        issue_part<128>(gBh + KCH, K, bufs + BUFB + OFF_BHI, tid);
        issue_part<128>(gBl + KCH, K, bufs + BUFB + OFF_BLO, tid);
        CP_COMMIT();
    }

    const int lrow   = lane & 15;
    const int lkhalf = (lane & 16) ? 16 : 0;   // byte offset selecting k+8 blocks

    for (int s = 0; s < nch; ++s) {
        CP_WAIT1();            // B(s) (and A(s) / A32(s)) resident
        __syncthreads();

        const uint32_t buf = bufs + (uint32_t)(s & 1) * BUFB;
        const uint32_t aHi = buf + OFF_AHI;
        const uint32_t aLo = buf + OFF_ALO;
        const uint32_t bHi = buf + OFF_BHI;
        const uint32_t bLo = buf + OFF_BLO;

        if (AFP32) {
            // Split staged fp32 chunk s into this stage's bf16 A tiles.
            convert_a32(dstag, aHi, aLo, tid);
            __syncthreads();   // conversion visible; staging buffer free
            // Refill staging with A32(s+1); lone group keeps wait-counts aligned.
            if (s + 1 < nch) issue_a32(gA32 + (s + 1) * KCH, K, stage, tid);
            CP_COMMIT();       // group {A32(s+1)}
        }

#pragma unroll
        for (int ks = 0; ks < 4; ++ks) {
            uint32_t ah[2][4], al[2][4], bh[2][4], bl[2][4];
#pragma unroll
            for (int mt = 0; mt < 2; ++mt) {
                int row = wm * 32 + mt * 16 + lrow;
                uint32_t boff = (uint32_t)(row * 128 + ks * 32 + lkhalf);
                uint32_t sw   = boff ^ ((boff >> 3) & 0x70);
                ldsm4(ah[mt][0], ah[mt][1], ah[mt][2], ah[mt][3], aHi + sw);
                ldsm4(al[mt][0], al[mt][1], al[mt][2], al[mt][3], aLo + sw);
            }
#pragma unroll
            for (int g = 0; g < 2; ++g) {
                int row = wn * 32 + g * 16 + lrow;
                uint32_t boff = (uint32_t)(row * 128 + ks * 32 + lkhalf);
                uint32_t sw   = boff ^ ((boff >> 3) & 0x70);
                ldsm4(bh[g][0], bh[g][1], bh[g][2], bh[g][3], bHi + sw);
                ldsm4(bl[g][0], bl[g][1], bl[g][2], bl[g][3], bLo + sw);
            }
#pragma unroll
            for (int mt = 0; mt < 2; ++mt)
#pragma unroll
                for (int nt = 0; nt < 4; ++nt) {
                    const int g = nt >> 1, e = nt & 1;
                    mma16816(acc[mt][nt], ah[mt], bh[g][e], bh[g][e + 2]);
                    mma16816(acc[mt][nt], ah[mt], bl[g][e], bl[g][e + 2]);
                    mma16816(acc[mt][nt], al[mt], bh[g][e], bh[g][e + 2]);
                }
        }

        __syncthreads();       // all warps done reading buf before refill

        if (s + 2 < nch) {
            if (AFP32) {
                issue_part<128>(gBh + (s + 2) * KCH, K, buf + OFF_BHI, tid);
                issue_part<128>(gBl + (s + 2) * KCH, K, buf + OFF_BLO, tid);
            } else {
                issue_part<64> (gAh + (s + 2) * KCH, K, buf + OFF_AHI, tid);
                issue_part<64> (gAl + (s + 2) * KCH, K, buf + OFF_ALO, tid);
                issue_part<128>(gBh + (s + 2) * KCH, K, buf + OFF_BHI, tid);
                issue_part<128>(gBl + (s + 2) * KCH, K, buf + OFF_BLO, tid);
            }
        }
        CP_COMMIT();           // group {B(s+2)} (possibly empty)
    }

    // Epilogue: fragment (m16n8) c0,c1 -> row gID, cols 2*tIG,+1 ; c2,c3 -> row gID+8
    const int gID = lane >> 2;
    const int tIG = lane & 3;
#pragma unroll
    for (int mt = 0; mt < 2; ++mt)
#pragma unroll
        for (int half = 0; half < 2; ++half) {
            const int m = m0 + wm * 32 + mt * 16 + gID + half * 8;
#pragma unroll
            for (int nt = 0; nt < 4; ++nt) {
                const int n = n0 + wn * 32 + nt * 8 + tIG * 2;
                float v0 = acc[mt][nt][half * 2 + 0];
                float v1 = acc[mt][nt][half * 2 + 1];
                if (dvec != nullptr) {
                    const float* up = U2 + (size_t)m * N + n;
                    v0 = fmaf(dvec[n],     up[0], v0);
                    v1 = fmaf(dvec[n + 1], up[1], v1);
                }
                float2 o = make_float2(v0, v1);
                *reinterpret_cast<float2*>(C + (size_t)m * N + n) = o;
            }
        }
}

// ---------------------------------------------------------------------------
// Per-batch inclusive cumsum of timesteps (16 blocks x 1024 threads).
// ---------------------------------------------------------------------------
__global__ __launch_bounds__(1024)
void tsum_kernel(const float* __restrict__ t, float* __restrict__ T)
{
    __shared__ float sh[SEQL];
    const int b = blockIdx.x, i = threadIdx.x;
    sh[i] = t[b * SEQL + i];
    __syncthreads();
#pragma unroll
    for (int off = 1; off < SEQL; off <<= 1) {
        float add = (i >= off) ? sh[i - off] : 0.0f;
        __syncthreads();
        sh[i] += add;
        __syncthreads();
    }
    T[b * SEQL + i] = sh[i];
}

// ---------------------------------------------------------------------------
// Parallel scan over L.
// Uses A_cum(l) = exp(Lam*step * T(l)) (CLIP_MAX never binds since Lam<0,
// Delta>=0), so z = gamma*Bu/(A_cum+1e-9) is element-wise and s = cumsum(z).
// Block (32 p-lanes, 8 l-threads); 16 chunks of 64 l; smem carry chain.
// grid (BSZ, PDIM/32). Writes x pre-split as bf16 hi/lo for GEMM2.
// ---------------------------------------------------------------------------
__global__ __launch_bounds__(256)
void s5_scan_par(const float* __restrict__ timesteps,
                 const float* __restrict__ Tg,
                 const float* __restrict__ Lambda_raw,
                 const float* __restrict__ log_step,
                 const float* __restrict__ Bu,
                 __nv_bfloat16* __restrict__ xhi,
                 __nv_bfloat16* __restrict__ xlo)
{
    const int b  = blockIdx.x;
    const int tx = threadIdx.x;                 // 0..31 (p lane)
    const int ty = threadIdx.y;                 // 0..7  (l group)
    const int p  = blockIdx.y * 32 + tx;

    __shared__ float t_sh[SEQL];
    __shared__ float T_sh[SEQL];
    __shared__ float part[2][8][33];
    __shared__ float carry[2][32];

    const int tid = ty * 32 + tx;
    for (int i = tid; i < SEQL; i += 256) {
        t_sh[i] = timesteps[b * SEQL + i];
        T_sh[i] = Tg[b * SEQL + i];
    }
    if (ty == 0) carry[0][tx] = 0.0f;

    float raw  = Lambda_raw[p];
    float sp   = fmaxf(raw, 0.0f) + log1pf(expf(-fabsf(raw)));
    float Lam  = -(sp + 1e-3f);
    float step = expf(log_step[p]);             // STEP_RESCALE == 1
    float K1   = Lam * step;
    float invLam = 1.0f / Lam;

    const size_t base = ((size_t)b * SEQL) * PDIM + p;

    float zt[8], ac[8];
    for (int c = 0; c < 16; ++c) {
        const int l0 = c * 64 + ty * 8;
        float lsum = 0.0f;
#pragma unroll
        for (int k = 0; k < 8; ++k) {
            const int l = l0 + k;
            float A_cum = __expf(K1 * T_sh[l]);
            float A_bar = __expf(K1 * t_sh[l]);
            float gamma = (A_bar - 1.0f) * invLam;   // |Lam| >= 1e-3 always
            float bu    = Bu[base + (size_t)l * PDIM];
            float z     = __fdividef(gamma * bu, A_cum + 1e-9f);
            lsum += z;
            zt[k] = lsum;        // inclusive local prefix
            ac[k] = A_cum;
        }
        part[c & 1][ty][tx] = lsum;
        __syncthreads();
        float cr = carry[c & 1][tx];
#pragma unroll
        for (int y = 0; y < 7; ++y)
            if (y < ty) cr += part[c & 1][y][tx];
        if (ty == 7) carry[(c + 1) & 1][tx] = cr + part[c & 1][7][tx];
#pragma unroll
        for (int k = 0; k < 8; ++k) {
            const int l = l0 + k;
            float x = ac[k] * (cr + zt[k]);
            __nv_bfloat16 h = __float2bfloat16(x);
            xhi[base + (size_t)l * PDIM] = h;
            xlo[base + (size_t)l * PDIM] =
                __float2bfloat16(x - __bfloat162float(h));
        }
    }
}

// ---------------------------------------------------------------------------
// Launch: split(B,C) + tsum -> GEMM1 (fused u-split) -> scan -> GEMM2
// Input order (metadata): u, timesteps, Lambda_raw, log_step, B, C, D
// ---------------------------------------------------------------------------
extern "C" void kernel_launch(void* const* d_in, const int* in_sizes, int n_in,
                              void* d_out, int out_size)
{
    const float* u          = (const float*)d_in[0];
    const float* timesteps  = (const float*)d_in[1];
    const float* Lambda_raw = (const float*)d_in[2];
    const float* log_step   = (const float*)d_in[3];
    const float* Bmat       = (const float*)d_in[4];
    const float* Cmat       = (const float*)d_in[5];
    const float* Dvec       = (const float*)d_in[6];
    float* out = (float*)d_out;

    float *Bu, *Tg;
    __nv_bfloat16 *xhi, *xlo, *Bhi, *Blo, *Chi, *Clo;
    cudaGetSymbolAddress((void**)&Bu,  g_Bu);
    cudaGetSymbolAddress((void**)&Tg,  g_T);
    cudaGetSymbolAddress((void**)&xhi, g_xhi);
    cudaGetSymbolAddress((void**)&xlo, g_xlo);
    cudaGetSymbolAddress((void**)&Bhi, g_Bhi);
    cudaGetSymbolAddress((void**)&Blo, g_Blo);
    cudaGetSymbolAddress((void**)&Chi, g_Chi);
    cudaGetSymbolAddress((void**)&Clo, g_Clo);

    cudaFuncSetAttribute(gemm_mma_kernel<true>,
                         cudaFuncAttributeMaxDynamicSharedMemorySize, SMEM_G1);
    cudaFuncSetAttribute(gemm_mma_kernel<false>,
                         cudaFuncAttributeMaxDynamicSharedMemorySize, SMEM_G2);

    // Prepass: split weight matrices, cumsum of t (all tiny)
    {
        int n4b = PDIM * HIN / 4;
        split_kernel<<<512, 256>>>((const float4*)Bmat, (uint2*)Bhi, (uint2*)Blo, n4b);
        int n4c = HOUT * PDIM / 4;
        split_kernel<<<512, 256>>>((const float4*)Cmat, (uint2*)Chi, (uint2*)Clo, n4c);
        tsum_kernel<<<BSZ, SEQL>>>(timesteps, Tg);
    }

    // GEMM1: Bu[M, P] = u[M, HIN] @ B[P, HIN]^T  (u split fused in-kernel)
    {
        dim3 grid(PDIM / 128, MROWS / 64);
        gemm_mma_kernel<true><<<grid, NTHR, SMEM_G1>>>(
            u, nullptr, nullptr, Bhi, Blo, Bu,
            MROWS, PDIM, HIN, nullptr, nullptr);
    }

    // Parallel scan: Bu -> x_seq (emitted pre-split as bf16 hi/lo)
    {
        dim3 grid(BSZ, PDIM / 32);
        dim3 blk(32, 8);
        s5_scan_par<<<grid, blk>>>(timesteps, Tg, Lambda_raw, log_step,
                                   Bu, xhi, xlo);
    }

    // GEMM2: ys[M, HOUT] = x[M, P] @ C[HOUT, P]^T + D * u
    {
        dim3 grid(HOUT / 128, MROWS / 64);
        gemm_mma_kernel<false><<<grid, NTHR, SMEM_G2>>>(
            nullptr, xhi, xlo, Chi, Clo, out,
            MROWS, HOUT, PDIM, Dvec, u);
    }
}